// round 7
// baseline (speedup 1.0000x reference)
#include <cuda_runtime.h>
#include <cuda_fp16.h>
#include <math.h>
#include <stdint.h>

#define NN_MAX 100000
#define NE_MAX 1600000
#define NB 592                      // persistent grid: 148 SMs x 4 blocks

// ---------------- Device scratch ----------------
__device__ __align__(16) __half g_h[(size_t)NN_MAX * 64];   // GEMM out -> gather src
__device__ __align__(16) __half g_a[(size_t)NN_MAX * 64];   // agg out  -> GEMM A src
__device__ float g_dinv[NN_MAX];
__device__ int   g_cnt[NN_MAX];
__device__ int   g_rowptr[NN_MAX + 1];
__device__ int   g_cursor[NN_MAX];
__device__ int   g_csr[NE_MAX];
__device__ __align__(16) float g_Wf[64 * 64];
__device__ __align__(16) float g_bf[64];
__device__ int   g_ei_is32;
__device__ unsigned long long g_state[512];    // lookback state
__device__ unsigned g_barArrive[4];            // zero-init; self-resetting
__device__ unsigned g_barGen[4];               // monotonic across replays

// ---------------- grid barrier (gen-counter; replay-safe) ----------------
__device__ __forceinline__ void gbar(int slot) {
    __syncthreads();
    if (threadIdx.x == 0) {
        __threadfence();
        unsigned g = ((volatile unsigned*)g_barGen)[slot];
        unsigned old = atomicAdd(&g_barArrive[slot], 1);
        if (old == NB - 1) {
            g_barArrive[slot] = 0;
            __threadfence();
            atomicAdd(&g_barGen[slot], 1);
        } else {
            while (((volatile unsigned*)g_barGen)[slot] == g) __nanosleep(64);
        }
        __threadfence();
    }
    __syncthreads();
}

__device__ __forceinline__ int edge_val(const int* __restrict__ w, size_t e, bool is32) {
    return is32 ? w[e] : w[2 * e];
}

// ---------------- persistent CSR build: prep | hist | scan | fill ----------------
__global__ __launch_bounds__(256) void csr_mega(
    const int* __restrict__ ei, int nwords, int n, int ne,
    const float* __restrict__ W3, const float* __restrict__ W4,
    const float* __restrict__ b3, const float* __restrict__ b4) {
    int t = threadIdx.x, b = blockIdx.x;
    int gtid = b * 256 + t;
    const int GSZ = NB * 256;

    // ---- P0: zero cnt/state, detect dtype, wfuse/bfuse ----
    for (int i = gtid; i < n; i += GSZ) g_cnt[i] = 0;
    if (gtid < 512) g_state[gtid] = 0ULL;
    if (b == NB - 1) {
        __shared__ int any;
        if (t == 0) any = 0;
        __syncthreads();
        int idx = 2 * t + 1;
        if (idx < nwords && ei[idx] != 0) atomicOr(&any, 1);
        __syncthreads();
        if (t == 0) g_ei_is32 = any;
    }
    for (int e2 = gtid; e2 < 64 * 64; e2 += GSZ) {
        int i = e2 >> 6, j = e2 & 63;
        float acc = 0.f;
        for (int k = 0; k < 256; k++) acc += W3[i * 256 + k] * W4[k * 64 + j];
        g_Wf[e2] = acc;
    }
    if (gtid < 64) {
        float acc = b4[gtid];
        for (int k = 0; k < 256; k++) acc += b3[k] * W4[k * 64 + gtid];
        g_bf[gtid] = acc;
    }
    gbar(0);

    // ---- P1: histogram of dst degrees ----
    {
        bool is32 = (g_ei_is32 != 0);
        for (int e = gtid; e < ne; e += GSZ) {
            int dst = edge_val(ei, (size_t)ne + e, is32);
            atomicAdd(&g_cnt[dst], 1);
        }
    }
    gbar(1);

    // ---- P2: decoupled-lookback exclusive scan (tiles of 1024, 4 elems/thread) ----
    {
        int ntiles = (n + 1023) >> 10;
        if (b < ntiles) {
            __shared__ int wsum[8];
            __shared__ int sexc;
            int lane = t & 31, wid = t >> 5;
            int base = b * 1024 + t * 4;
            int v[4];
#pragma unroll
            for (int q = 0; q < 4; q++) v[q] = (base + q < n) ? g_cnt[base + q] : 0;
            int tsum = v[0] + v[1] + v[2] + v[3];
            int x = tsum;
#pragma unroll
            for (int off = 1; off < 32; off <<= 1) {
                int y = __shfl_up_sync(0xffffffffu, x, off);
                if (lane >= off) x += y;
            }
            if (lane == 31) wsum[wid] = x;
            __syncthreads();
            if (wid == 0) {
                int s = (lane < 8) ? wsum[lane] : 0;
#pragma unroll
                for (int off = 1; off < 8; off <<= 1) {
                    int y = __shfl_up_sync(0xffffffffu, s, off);
                    if (lane >= off) s += y;
                }
                if (lane < 8) wsum[lane] = s;
            }
            __syncthreads();
            int wpre = wid ? wsum[wid - 1] : 0;
            int exc_t = wpre + x - tsum;
            int total = wsum[7];

            if (t == 0) {
                unsigned long long pub = (b == 0)
                    ? ((2ULL << 32) | (unsigned)total)
                    : ((1ULL << 32) | (unsigned)total);
                atomicExch(&g_state[b], pub);
            }
            if (wid == 0) {
                int exc = 0;
                if (b > 0) {
                    int p = b - 1;
                    while (true) {
                        int idx = p - lane;
                        bool valid = idx >= 0;
                        unsigned long long s;
                        do {
                            s = valid ? atomicAdd(&g_state[idx], 0ULL) : (2ULL << 32);
                        } while (__any_sync(0xffffffffu, (unsigned)(s >> 32) == 0u));
                        unsigned pm = __ballot_sync(0xffffffffu, valid && (unsigned)(s >> 32) == 2u);
                        int contrib;
                        if (pm) {
                            int fp = __ffs(pm) - 1;
                            contrib = (valid && lane <= fp) ? (int)(unsigned)s : 0;
                        } else {
                            contrib = valid ? (int)(unsigned)s : 0;
                        }
#pragma unroll
                        for (int o = 16; o > 0; o >>= 1)
                            contrib += __shfl_xor_sync(0xffffffffu, contrib, o);
                        exc += contrib;
                        if (pm) break;
                        p -= 32;
                        if (p < 0) break;
                    }
                }
                if (lane == 0) {
                    sexc = exc;
                    atomicExch(&g_state[b], (2ULL << 32) | (unsigned)(exc + total));
                }
            }
            __syncthreads();
            int run = sexc + exc_t;
#pragma unroll
            for (int q = 0; q < 4; q++) {
                int i = base + q;
                if (i < n) {
                    g_rowptr[i] = run;
                    g_cursor[i] = run;
                    g_dinv[i] = rsqrtf((float)v[q] + 1.0f);
                }
                run += v[q];
            }
            if (t == 0 && b == 0) g_rowptr[n] = ne;
        }
    }
    gbar(2);

    // ---- P3: fill CSR ----
    {
        bool is32 = (g_ei_is32 != 0);
        for (int e = gtid; e < ne; e += GSZ) {
            int src = edge_val(ei, (size_t)e, is32);
            int dst = edge_val(ei, (size_t)ne + e, is32);
            int p = atomicAdd(&g_cursor[dst], 1);
            g_csr[p] = src;
        }
    }
}

// ---------------- TF32 tensor-core GEMM (single-term), templated input dtype ----------------
#define MMA_TF32(d, A0, A1, A2, A3, B0, B1)                                     \
    asm("mma.sync.aligned.m16n8k8.row.col.f32.tf32.tf32.f32 "                   \
        "{%0,%1,%2,%3}, {%4,%5,%6,%7}, {%8,%9}, {%0,%1,%2,%3};"                 \
        : "+f"(d[0]), "+f"(d[1]), "+f"(d[2]), "+f"(d[3])                        \
        : "r"(A0), "r"(A1), "r"(A2), "r"(A3), "r"(B0), "r"(B1))

__device__ __forceinline__ uint32_t f2tf32(float f) {
    uint32_t u;
    asm("cvt.rna.tf32.f32 %0, %1;" : "=r"(u) : "f"(f));
    return u;
}

__device__ __forceinline__ void load16(const float* p, float* v) {
    float4 a = *(const float4*)p;
    float4 b = *(const float4*)(p + 4);
    float4 c = *(const float4*)(p + 8);
    float4 d = *(const float4*)(p + 12);
    v[0]=a.x; v[1]=a.y; v[2]=a.z; v[3]=a.w;
    v[4]=b.x; v[5]=b.y; v[6]=b.z; v[7]=b.w;
    v[8]=c.x; v[9]=c.y; v[10]=c.z; v[11]=c.w;
    v[12]=d.x; v[13]=d.y; v[14]=d.z; v[15]=d.w;
}
__device__ __forceinline__ void load16(const __half* p, float* v) {
    uint4 u0 = *(const uint4*)p;
    uint4 u1 = *(const uint4*)(p + 8);
    const half2* h0 = (const half2*)&u0;
    const half2* h1 = (const half2*)&u1;
#pragma unroll
    for (int i = 0; i < 4; i++) {
        float2 f0 = __half22float2(h0[i]);
        float2 f1 = __half22float2(h1[i]);
        v[2*i] = f0.x;   v[2*i+1] = f0.y;
        v[8+2*i] = f1.x; v[8+2*i+1] = f1.y;
    }
}

template <int K, int EPI, typename InT, typename OutT>
__global__ __launch_bounds__(256, 2) void gemm_mma(
    const InT* __restrict__ A, const float* __restrict__ W,
    const float* __restrict__ extra, OutT* __restrict__ C, int M) {
    extern __shared__ uint32_t smem[];
    uint32_t* sB = smem;                          // K*64 words, fragment order
    float*    As = (float*)(smem + K * 64);       // 128 x 33 (padded)

    int tid = threadIdx.x, lane = tid & 31, warp = tid >> 5;
    int rowBase = blockIdx.x * 128;
    int gr = lane >> 2;
    int gc = lane & 3;

    for (int i = tid; i < K * 64; i += 256) {
        int k = i >> 6, n = i & 63;
        int slot = (((k >> 3) * 8 + (n >> 3)) * 32 + ((n & 7) * 4 + (k & 3))) * 2 + ((k & 7) >> 2);
        sB[slot] = f2tf32(W[i]);
    }

    float acc[8][4];
#pragma unroll
    for (int nt = 0; nt < 8; nt++)
#pragma unroll
        for (int r = 0; r < 4; r++) acc[nt][r] = 0.f;

    int rowLoc = warp * 16 + gr;
    __syncthreads();

    for (int kc = 0; kc < K; kc += 32) {
        {
            int row = tid >> 1;
            int h = (tid & 1) * 16;
            int grow = rowBase + row;
            float v[16];
            if (grow < M) {
                load16(A + (size_t)grow * K + kc + h, v);
            } else {
#pragma unroll
                for (int q = 0; q < 16; q++) v[q] = 0.f;
            }
            float* dst = As + row * 33 + h;
#pragma unroll
            for (int q = 0; q < 16; q++) dst[q] = v[q];
        }
        __syncthreads();

#pragma unroll
        for (int k8 = 0; k8 < 4; k8++) {
            int col = k8 * 8 + gc;
            uint32_t ah0 = f2tf32(As[rowLoc * 33 + col]);
            uint32_t ah1 = f2tf32(As[(rowLoc + 8) * 33 + col]);
            uint32_t ah2 = f2tf32(As[rowLoc * 33 + col + 4]);
            uint32_t ah3 = f2tf32(As[(rowLoc + 8) * 33 + col + 4]);
            int gk8 = (kc >> 3) + k8;
#pragma unroll
            for (int nt = 0; nt < 8; nt++) {
                int sbase = ((gk8 * 8 + nt) * 32 + lane) * 2;
                MMA_TF32(acc[nt], ah0, ah1, ah2, ah3, sB[sbase], sB[sbase + 1]);
            }
        }
        __syncthreads();
    }

    int row0 = rowBase + warp * 16 + gr;
    int row1 = row0 + 8;

    if (EPI == 0) {
        __half* Ch = (__half*)C;
        if (row0 < M) {
#pragma unroll
            for (int nt = 0; nt < 8; nt++)
                *(half2*)(Ch + (size_t)row0 * 64 + nt * 8 + 2 * gc) =
                    __floats2half2_rn(acc[nt][0], acc[nt][1]);
        }
        if (row1 < M) {
#pragma unroll
            for (int nt = 0; nt < 8; nt++)
                *(half2*)(Ch + (size_t)row1 * 64 + nt * 8 + 2 * gc) =
                    __floats2half2_rn(acc[nt][2], acc[nt][3]);
        }
    } else {
        float* Cf = (float*)C;
        float v0[16], v1[16];
#pragma unroll
        for (int nt = 0; nt < 8; nt++) {
            float2 bb = *(const float2*)(extra + nt * 8 + 2 * gc);
            v0[2*nt]   = acc[nt][0] + bb.x;
            v0[2*nt+1] = acc[nt][1] + bb.y;
            v1[2*nt]   = acc[nt][2] + bb.x;
            v1[2*nt+1] = acc[nt][3] + bb.y;
        }
        float m0 = -1e30f, m1 = -1e30f;
#pragma unroll
        for (int i = 0; i < 16; i++) { m0 = fmaxf(m0, v0[i]); m1 = fmaxf(m1, v1[i]); }
        m0 = fmaxf(m0, __shfl_xor_sync(0xffffffffu, m0, 1));
        m0 = fmaxf(m0, __shfl_xor_sync(0xffffffffu, m0, 2));
        m1 = fmaxf(m1, __shfl_xor_sync(0xffffffffu, m1, 1));
        m1 = fmaxf(m1, __shfl_xor_sync(0xffffffffu, m1, 2));
        float s0 = 0.f, s1 = 0.f;
#pragma unroll
        for (int i = 0; i < 16; i++) { s0 += expf(v0[i] - m0); s1 += expf(v1[i] - m1); }
        s0 += __shfl_xor_sync(0xffffffffu, s0, 1);
        s0 += __shfl_xor_sync(0xffffffffu, s0, 2);
        s1 += __shfl_xor_sync(0xffffffffu, s1, 1);
        s1 += __shfl_xor_sync(0xffffffffu, s1, 2);
        float lse0 = m0 + logf(s0);
        float lse1 = m1 + logf(s1);
        if (row0 < M) {
#pragma unroll
            for (int nt = 0; nt < 8; nt++)
                *(float2*)(Cf + (size_t)row0 * 64 + nt * 8 + 2 * gc) =
                    make_float2(v0[2*nt] - lse0, v0[2*nt+1] - lse0);
        }
        if (row1 < M) {
#pragma unroll
            for (int nt = 0; nt < 8; nt++)
                *(float2*)(Cf + (size_t)row1 * 64 + nt * 8 + 2 * gc) =
                    make_float2(v1[2*nt] - lse1, v1[2*nt+1] - lse1);
        }
    }
}

// ---------------- Aggregation (fp16 in, fp16 out) ----------------
__global__ void agg_k(const __half* __restrict__ hs, const float* __restrict__ bias,
                      __half* __restrict__ out, int M) {
    __shared__ int   sidx[8][32];
    __shared__ float sds[8][32];
    int wib = threadIdx.x >> 5;
    int w = (blockIdx.x * blockDim.x + threadIdx.x) >> 5;
    int lane = threadIdx.x & 31;
    if (w >= M) return;

    int start = g_rowptr[w];
    int end = g_rowptr[w + 1];
    float rd = g_dinv[w];

    float2 selfv = __half22float2(((const half2*)(hs + (size_t)w * 64))[lane]);
    float a0 = rd * selfv.x, a1 = rd * selfv.y;
    float b0 = 0.f, b1 = 0.f, c0 = 0.f, c1 = 0.f, d0 = 0.f, d1 = 0.f;
    float e0 = 0.f, e1 = 0.f, f0 = 0.f, f1 = 0.f;
    float g0 = 0.f, g1 = 0.f, h0 = 0.f, h1 = 0.f;

    for (int base = start; base < end; base += 32) {
        int e = base + lane;
        __syncwarp();
        int s = (e < end) ? g_csr[e] : 0;
        sidx[wib][lane] = s;
        sds[wib][lane] = (e < end) ? g_dinv[s] : 0.f;
        __syncwarp();
        int cnt = min(32, end - base);
        int j = 0;
        for (; j + 8 <= cnt; j += 8) {
            half2 v0 = ((const half2*)(hs + (size_t)sidx[wib][j + 0] * 64))[lane];
            half2 v1 = ((const half2*)(hs + (size_t)sidx[wib][j + 1] * 64))[lane];
            half2 v2 = ((const half2*)(hs + (size_t)sidx[wib][j + 2] * 64))[lane];
            half2 v3 = ((const half2*)(hs + (size_t)sidx[wib][j + 3] * 64))[lane];
            half2 v4 = ((const half2*)(hs + (size_t)sidx[wib][j + 4] * 64))[lane];
            half2 v5 = ((const half2*)(hs + (size_t)sidx[wib][j + 5] * 64))[lane];
            half2 v6 = ((const half2*)(hs + (size_t)sidx[wib][j + 6] * 64))[lane];
            half2 v7 = ((const half2*)(hs + (size_t)sidx[wib][j + 7] * 64))[lane];
            float2 f0v = __half22float2(v0), f1v = __half22float2(v1);
            float2 f2v = __half22float2(v2), f3v = __half22float2(v3);
            float2 f4v = __half22float2(v4), f5v = __half22float2(v5);
            float2 f6v = __half22float2(v6), f7v = __half22float2(v7);
            a0 = fmaf(f0v.x, sds[wib][j+0], a0); a1 = fmaf(f0v.y, sds[wib][j+0], a1);
            b0 = fmaf(f1v.x, sds[wib][j+1], b0); b1 = fmaf(f1v.y, sds[wib][j+1], b1);
            c0 = fmaf(f2v.x, sds[wib][j+2], c0); c1 = fmaf(f2v.y, sds[wib][j+2], c1);
            d0 = fmaf(f3v.x, sds[wib][j+3], d0); d1 = fmaf(f3v.y, sds[wib][j+3], d1);
            e0 = fmaf(f4v.x, sds[wib][j+4], e0); e1 = fmaf(f4v.y, sds[wib][j+4], e1);
            f0 = fmaf(f5v.x, sds[wib][j+5], f0); f1 = fmaf(f5v.y, sds[wib][j+5], f1);
            g0 = fmaf(f6v.x, sds[wib][j+6], g0); g1 = fmaf(f6v.y, sds[wib][j+6], g1);
            h0 = fmaf(f7v.x, sds[wib][j+7], h0); h1 = fmaf(f7v.y, sds[wib][j+7], h1);
        }
        for (; j < cnt; j++) {
            float2 fv = __half22float2(((const half2*)(hs + (size_t)sidx[wib][j] * 64))[lane]);
            float ss = sds[wib][j];
            a0 = fmaf(fv.x, ss, a0);
            a1 = fmaf(fv.y, ss, a1);
        }
    }
    a0 = ((a0 + b0) + (c0 + d0)) + ((e0 + f0) + (g0 + h0));
    a1 = ((a1 + b1) + (c1 + d1)) + ((e1 + f1) + (g1 + h1));

    float2 bb = ((const float2*)bias)[lane];
    float o0 = fmaxf(fmaf(a0, rd, bb.x), 0.f);
    float o1 = fmaxf(fmaf(a1, rd, bb.y), 0.f);
    ((half2*)(out + (size_t)w * 64))[lane] = __floats2half2_rn(o0, o1);
}

// ---------------- Host launcher ----------------
extern "C" void kernel_launch(void* const* d_in, const int* in_sizes, int n_in,
                              void* d_out, int out_size) {
    const float* x  = (const float*)d_in[0];
    const int*   ei = (const int*)d_in[1];
    const float* W1 = (const float*)d_in[2];
    const float* b1 = (const float*)d_in[3];
    const float* W2 = (const float*)d_in[4];
    const float* b2 = (const float*)d_in[5];
    const float* W3 = (const float*)d_in[6];
    const float* b3 = (const float*)d_in[7];
    const float* W4 = (const float*)d_in[8];
    const float* b4 = (const float*)d_in[9];
    float* out = (float*)d_out;

    const int M = in_sizes[0] / 128;
    const int E = in_sizes[1] / 2;

    __half *hb, *ab;
    float *Wf, *bf;
    cudaGetSymbolAddress((void**)&hb, g_h);
    cudaGetSymbolAddress((void**)&ab, g_a);
    cudaGetSymbolAddress((void**)&Wf, g_Wf);
    cudaGetSymbolAddress((void**)&bf, g_bf);

    const int smem128 = 128 * 64 * 4 + 128 * 33 * 4;   // 49664 B
    const int smem64  = 64 * 64 * 4 + 128 * 33 * 4;    // 33280 B
    cudaFuncSetAttribute((const void*)gemm_mma<128, 0, float, __half>,
                         cudaFuncAttributeMaxDynamicSharedMemorySize, smem128);
    cudaFuncSetAttribute((const void*)gemm_mma<64, 0, __half, __half>,
                         cudaFuncAttributeMaxDynamicSharedMemorySize, smem64);
    cudaFuncSetAttribute((const void*)gemm_mma<64, 1, __half, float>,
                         cudaFuncAttributeMaxDynamicSharedMemorySize, smem64);

    const int gemmBlocks = (M + 127) / 128;
    const int warpBlocks = (M * 32 + 255) / 256;

    // 1) CSR build, weight fusion, dinv — one persistent kernel.
    csr_mega<<<NB, 256>>>(ei, 2 * E, M, E, W3, W4, b3, b4);
    // 2) Layer 1 GEMM (fp32 x, fp16 out)
    gemm_mma<128, 0, float, __half><<<gemmBlocks, 256, smem128>>>(x, W1, nullptr, hb, M);
    // 3) agg1
    agg_k<<<warpBlocks, 256>>>(hb, b1, ab, M);
    // 4) Layer 2 GEMM (fp16 in/out)  <- ncu capture slot
    gemm_mma<64, 0, __half, __half><<<gemmBlocks, 256, smem64>>>(ab, W2, nullptr, hb, M);
    // 5) agg2
    agg_k<<<warpBlocks, 256>>>(hb, b2, ab, M);
    // 6) fused layers 3+4 with bias + log-softmax epilogue
    gemm_mma<64, 1, __half, float><<<gemmBlocks, 256, smem64>>>(ab, Wf, bf, out, M);
}

// round 8
// speedup vs baseline: 1.2350x; 1.2350x over previous
#include <cuda_runtime.h>
#include <cuda_fp16.h>
#include <math.h>
#include <stdint.h>

#define NN_MAX 100000
#define NE_MAX 1600000

// ---------------- Device scratch ----------------
__device__ __align__(16) __half g_h[(size_t)NN_MAX * 64];   // GEMM out -> gather src
__device__ __align__(16) __half g_a[(size_t)NN_MAX * 64];   // agg out  -> GEMM A src
__device__ float g_dinv[NN_MAX];
__device__ int   g_cnt[NN_MAX];
__device__ int   g_rowptr[NN_MAX + 1];
__device__ int   g_cursor[NN_MAX];
__device__ int   g_csr[NE_MAX];
__device__ __align__(16) float g_Wf[64 * 64];
__device__ __align__(16) float g_bf[64];
__device__ int   g_ei_is32;
__device__ int   g_ticket;
__device__ unsigned long long g_state[128];

// ---------------- prep: zero cnt + detect dtype + reset scan state + W3@W4 fusion ----------
__global__ void prep_k(const int* __restrict__ ei, int nwords, int M,
                       const float* __restrict__ W3, const float* __restrict__ W4,
                       const float* __restrict__ b3, const float* __restrict__ b4) {
    int b = blockIdx.x, t = threadIdx.x;
    int NBZ = (M + 255) >> 8;
    if (b < NBZ) {
        int i = b * 256 + t;
        if (i < M) g_cnt[i] = 0;
        return;
    }
    if (b == NBZ) {
        __shared__ int any;
        if (t == 0) { any = 0; g_ticket = 0; }
        __syncthreads();
        int idx = 2 * t + 1;                       // odd words: 0 iff int64 (<2^31)
        if (idx < nwords && ei[idx] != 0) atomicOr(&any, 1);
        if (t < 128) g_state[t] = 0ULL;
        if (t < 64) {
            float acc = b4[t];
            for (int k = 0; k < 256; k++) acc += b3[k] * W4[k * 64 + t];
            g_bf[t] = acc;
        }
        __syncthreads();
        if (t == 0) g_ei_is32 = any;
        return;
    }
    int e = (b - NBZ - 1) * 256 + t;
    int i = e >> 6, j = e & 63;
    float acc = 0.f;
    for (int k = 0; k < 256; k++) acc += W3[i * 256 + k] * W4[k * 64 + j];
    g_Wf[e] = acc;
}

__device__ __forceinline__ int edge_val(const int* __restrict__ w, size_t e, bool is32) {
    return is32 ? w[e] : w[2 * e];
}

__global__ void hist_k(const int* __restrict__ w, int ne) {
    int e = blockIdx.x * blockDim.x + threadIdx.x;
    if (e < ne) {
        bool is32 = (g_ei_is32 != 0);
        int dst = edge_val(w, (size_t)ne + e, is32);
        atomicAdd(&g_cnt[dst], 1);
    }
}

// ---------------- single-pass decoupled-lookback scan ----------------
__global__ void scan_k(int n, int ne) {
    __shared__ int wsum[32];
    __shared__ int sbid;
    __shared__ int sexc;
    int t = threadIdx.x, lane = t & 31, wid = t >> 5;
    if (t == 0) sbid = atomicAdd(&g_ticket, 1);
    __syncthreads();
    int bid = sbid;
    int i = bid * 1024 + t;
    int v = (i < n) ? g_cnt[i] : 0;
    int x = v;
#pragma unroll
    for (int off = 1; off < 32; off <<= 1) {
        int y = __shfl_up_sync(0xffffffffu, x, off);
        if (lane >= off) x += y;
    }
    if (lane == 31) wsum[wid] = x;
    __syncthreads();
    if (wid == 0) {
        int s = wsum[lane];
#pragma unroll
        for (int off = 1; off < 32; off <<= 1) {
            int y = __shfl_up_sync(0xffffffffu, s, off);
            if (lane >= off) s += y;
        }
        wsum[lane] = s;
    }
    __syncthreads();
    int wpre = wid ? wsum[wid - 1] : 0;
    int incl = wpre + x;
    int total = wsum[31];

    if (t == 0) {
        unsigned long long pub = (bid == 0)
            ? ((2ULL << 32) | (unsigned)total)
            : ((1ULL << 32) | (unsigned)total);
        atomicExch(&g_state[bid], pub);
    }
    if (wid == 0) {
        int exc = 0;
        if (bid > 0) {
            int p = bid - 1;
            while (true) {
                int idx = p - lane;
                bool valid = idx >= 0;
                unsigned long long s;
                do {
                    s = valid ? atomicAdd(&g_state[idx], 0ULL) : (2ULL << 32);
                } while (__any_sync(0xffffffffu, (unsigned)(s >> 32) == 0u));
                unsigned pm = __ballot_sync(0xffffffffu, valid && (unsigned)(s >> 32) == 2u);
                int contrib;
                if (pm) {
                    int fp = __ffs(pm) - 1;
                    contrib = (valid && lane <= fp) ? (int)(unsigned)s : 0;
                } else {
                    contrib = valid ? (int)(unsigned)s : 0;
                }
#pragma unroll
                for (int o = 16; o > 0; o >>= 1) contrib += __shfl_xor_sync(0xffffffffu, contrib, o);
                exc += contrib;
                if (pm) break;
                p -= 32;
                if (p < 0) break;
            }
        }
        if (lane == 0) {
            sexc = exc;
            atomicExch(&g_state[bid], (2ULL << 32) | (unsigned)(exc + total));
        }
    }
    __syncthreads();
    int rp = sexc + incl - v;
    if (i < n) {
        g_rowptr[i] = rp;
        g_cursor[i] = rp;
        g_dinv[i] = rsqrtf((float)v + 1.0f);
    }
    if (t == 0 && bid == 0) g_rowptr[n] = ne;
}

__global__ void fill_k(const int* __restrict__ w, int ne) {
    int e = blockIdx.x * blockDim.x + threadIdx.x;
    if (e < ne) {
        bool is32 = (g_ei_is32 != 0);
        int src = edge_val(w, (size_t)e, is32);
        int dst = edge_val(w, (size_t)ne + e, is32);
        int p = atomicAdd(&g_cursor[dst], 1);
        g_csr[p] = src;
    }
}

// ---------------- fp16 tensor-core GEMM: mma.m16n8k16 + ldmatrix ----------------
// C[M x 64] = A[M x K] @ W[K x 64]. A, W converted to half. fp32 accumulate.
// EPI 0: C (half). EPI 1: C (float) = log_softmax(A@W + bias).
#define MMA_F16(d, A0, A1, A2, A3, B0, B1)                                      \
    asm("mma.sync.aligned.m16n8k16.row.col.f32.f16.f16.f32 "                    \
        "{%0,%1,%2,%3}, {%4,%5,%6,%7}, {%8,%9}, {%0,%1,%2,%3};"                 \
        : "+f"(d[0]), "+f"(d[1]), "+f"(d[2]), "+f"(d[3])                        \
        : "r"(A0), "r"(A1), "r"(A2), "r"(A3), "r"(B0), "r"(B1))

template <int K, int EPI, typename InT, typename OutT>
__global__ __launch_bounds__(256, 3) void gemm_mma(
    const InT* __restrict__ A, const float* __restrict__ W,
    const float* __restrict__ extra, OutT* __restrict__ C, int M) {
    constexpr int ASTRIDE = K + 8;                // halfs
    extern __shared__ uint32_t smem[];
    uint32_t* sB = smem;                          // (K/16)*8 frags x 32 lanes x 2 regs
    __half*   As = (__half*)(smem + K * 32);      // 128 x ASTRIDE halfs

    int tid = threadIdx.x, lane = tid & 31, warp = tid >> 5;
    int rowBase = blockIdx.x * 128;
    int gr = lane >> 2;
    int gc = lane & 3;

    // Stage B fragments: frag f covers k16=f>>3 (16 k's), nf=f&7 (8 n's).
    // word i = (f*32+lane)*2 + r  -> half2( W[k][n], W[k+1][n] ), k = k16*16+(lane&3)*2+r*8,
    // n = nf*8 + (lane>>2).
    for (int i = tid; i < K * 32; i += 256) {
        int f = i >> 6, within = i & 63;
        int bl = within >> 1, r = within & 1;
        int k = (f >> 3) * 16 + (bl & 3) * 2 + r * 8;
        int n = (f & 7) * 8 + (bl >> 2);
        half2 h = __floats2half2_rn(W[k * 64 + n], W[(k + 1) * 64 + n]);
        sB[i] = *(uint32_t*)&h;
    }

    // Stage A tile: 128 rows x K halfs (thread: row=tid>>1, half-range (tid&1)*K/2).
    {
        int row = tid >> 1;
        int off = (tid & 1) * (K / 2);
        int grow = rowBase + row;
        half2* dst = (half2*)(As + row * ASTRIDE + off);
        if (grow < M) {
            if constexpr (sizeof(InT) == 4) {
                const float4* src = (const float4*)((const float*)A + (size_t)grow * K + off);
#pragma unroll
                for (int q = 0; q < K / 8; q++) {
                    float4 v = src[q];
                    dst[2 * q]     = __floats2half2_rn(v.x, v.y);
                    dst[2 * q + 1] = __floats2half2_rn(v.z, v.w);
                }
            } else {
                const uint4* src = (const uint4*)((const __half*)A + (size_t)grow * K + off);
#pragma unroll
                for (int q = 0; q < K / 16; q++) {
                    uint4 v = src[q];
                    ((uint4*)dst)[q] = v;
                }
            }
        } else {
#pragma unroll
            for (int q = 0; q < K / 4; q++) dst[q] = __floats2half2_rn(0.f, 0.f);
        }
    }

    float acc[8][4];
#pragma unroll
    for (int nt = 0; nt < 8; nt++)
#pragma unroll
        for (int r = 0; r < 4; r++) acc[nt][r] = 0.f;

    int rowLoc = warp * 16;
    __syncthreads();

    // ldmatrix address for this lane (constant row/col-offset pattern across kc).
    int lrow = rowLoc + (lane & 15);
    int lcol = (lane >> 4) << 3;

#pragma unroll
    for (int kc16 = 0; kc16 < K / 16; kc16++) {
        uint32_t a0, a1, a2, a3;
        uint32_t addr = (uint32_t)__cvta_generic_to_shared(
            &As[lrow * ASTRIDE + kc16 * 16 + lcol]);
        asm volatile("ldmatrix.sync.aligned.m8n8.x4.shared.b16 {%0,%1,%2,%3}, [%4];"
                     : "=r"(a0), "=r"(a1), "=r"(a2), "=r"(a3) : "r"(addr));
#pragma unroll
        for (int nt = 0; nt < 8; nt++) {
            int sbase = ((kc16 * 8 + nt) * 32 + lane) * 2;
            MMA_F16(acc[nt], a0, a1, a2, a3, sB[sbase], sB[sbase + 1]);
        }
    }

    int row0 = rowBase + rowLoc + gr;
    int row1 = row0 + 8;

    if (EPI == 0) {
        __half* Ch = (__half*)C;
        if (row0 < M) {
#pragma unroll
            for (int nt = 0; nt < 8; nt++)
                *(half2*)(Ch + (size_t)row0 * 64 + nt * 8 + 2 * gc) =
                    __floats2half2_rn(acc[nt][0], acc[nt][1]);
        }
        if (row1 < M) {
#pragma unroll
            for (int nt = 0; nt < 8; nt++)
                *(half2*)(Ch + (size_t)row1 * 64 + nt * 8 + 2 * gc) =
                    __floats2half2_rn(acc[nt][2], acc[nt][3]);
        }
    } else {
        float* Cf = (float*)C;
        float v0[16], v1[16];
#pragma unroll
        for (int nt = 0; nt < 8; nt++) {
            float2 bb = *(const float2*)(extra + nt * 8 + 2 * gc);
            v0[2*nt]   = acc[nt][0] + bb.x;
            v0[2*nt+1] = acc[nt][1] + bb.y;
            v1[2*nt]   = acc[nt][2] + bb.x;
            v1[2*nt+1] = acc[nt][3] + bb.y;
        }
        float m0 = -1e30f, m1 = -1e30f;
#pragma unroll
        for (int i = 0; i < 16; i++) { m0 = fmaxf(m0, v0[i]); m1 = fmaxf(m1, v1[i]); }
        m0 = fmaxf(m0, __shfl_xor_sync(0xffffffffu, m0, 1));
        m0 = fmaxf(m0, __shfl_xor_sync(0xffffffffu, m0, 2));
        m1 = fmaxf(m1, __shfl_xor_sync(0xffffffffu, m1, 1));
        m1 = fmaxf(m1, __shfl_xor_sync(0xffffffffu, m1, 2));
        float s0 = 0.f, s1 = 0.f;
#pragma unroll
        for (int i = 0; i < 16; i++) { s0 += expf(v0[i] - m0); s1 += expf(v1[i] - m1); }
        s0 += __shfl_xor_sync(0xffffffffu, s0, 1);
        s0 += __shfl_xor_sync(0xffffffffu, s0, 2);
        s1 += __shfl_xor_sync(0xffffffffu, s1, 1);
        s1 += __shfl_xor_sync(0xffffffffu, s1, 2);
        float lse0 = m0 + logf(s0);
        float lse1 = m1 + logf(s1);
        if (row0 < M) {
#pragma unroll
            for (int nt = 0; nt < 8; nt++)
                *(float2*)(Cf + (size_t)row0 * 64 + nt * 8 + 2 * gc) =
                    make_float2(v0[2*nt] - lse0, v0[2*nt+1] - lse0);
        }
        if (row1 < M) {
#pragma unroll
            for (int nt = 0; nt < 8; nt++)
                *(float2*)(Cf + (size_t)row1 * 64 + nt * 8 + 2 * gc) =
                    make_float2(v1[2*nt] - lse1, v1[2*nt+1] - lse1);
        }
    }
}

// ---------------- Aggregation (fp16 in, fp16 out) ----------------
__global__ void agg_k(const __half* __restrict__ hs, const float* __restrict__ bias,
                      __half* __restrict__ out, int M) {
    __shared__ int   sidx[8][32];
    __shared__ float sds[8][32];
    int wib = threadIdx.x >> 5;
    int w = (blockIdx.x * blockDim.x + threadIdx.x) >> 5;
    int lane = threadIdx.x & 31;
    if (w >= M) return;

    int start = g_rowptr[w];
    int end = g_rowptr[w + 1];
    float rd = g_dinv[w];

    float2 selfv = __half22float2(((const half2*)(hs + (size_t)w * 64))[lane]);
    float a0 = rd * selfv.x, a1 = rd * selfv.y;
    float b0 = 0.f, b1 = 0.f, c0 = 0.f, c1 = 0.f, d0 = 0.f, d1 = 0.f;
    float e0 = 0.f, e1 = 0.f, f0 = 0.f, f1 = 0.f;
    float g0 = 0.f, g1 = 0.f, h0 = 0.f, h1 = 0.f;

    for (int base = start; base < end; base += 32) {
        int e = base + lane;
        __syncwarp();
        int s = (e < end) ? g_csr[e] : 0;
        sidx[wib][lane] = s;
        sds[wib][lane] = (e < end) ? g_dinv[s] : 0.f;
        __syncwarp();
        int cnt = min(32, end - base);
        int j = 0;
        for (; j + 8 <= cnt; j += 8) {
            half2 v0 = ((const half2*)(hs + (size_t)sidx[wib][j + 0] * 64))[lane];
            half2 v1 = ((const half2*)(hs + (size_t)sidx[wib][j + 1] * 64))[lane];
            half2 v2 = ((const half2*)(hs + (size_t)sidx[wib][j + 2] * 64))[lane];
            half2 v3 = ((const half2*)(hs + (size_t)sidx[wib][j + 3] * 64))[lane];
            half2 v4 = ((const half2*)(hs + (size_t)sidx[wib][j + 4] * 64))[lane];
            half2 v5 = ((const half2*)(hs + (size_t)sidx[wib][j + 5] * 64))[lane];
            half2 v6 = ((const half2*)(hs + (size_t)sidx[wib][j + 6] * 64))[lane];
            half2 v7 = ((const half2*)(hs + (size_t)sidx[wib][j + 7] * 64))[lane];
            float2 f0v = __half22float2(v0), f1v = __half22float2(v1);
            float2 f2v = __half22float2(v2), f3v = __half22float2(v3);
            float2 f4v = __half22float2(v4), f5v = __half22float2(v5);
            float2 f6v = __half22float2(v6), f7v = __half22float2(v7);
            a0 = fmaf(f0v.x, sds[wib][j+0], a0); a1 = fmaf(f0v.y, sds[wib][j+0], a1);
            b0 = fmaf(f1v.x, sds[wib][j+1], b0); b1 = fmaf(f1v.y, sds[wib][j+1], b1);
            c0 = fmaf(f2v.x, sds[wib][j+2], c0); c1 = fmaf(f2v.y, sds[wib][j+2], c1);
            d0 = fmaf(f3v.x, sds[wib][j+3], d0); d1 = fmaf(f3v.y, sds[wib][j+3], d1);
            e0 = fmaf(f4v.x, sds[wib][j+4], e0); e1 = fmaf(f4v.y, sds[wib][j+4], e1);
            f0 = fmaf(f5v.x, sds[wib][j+5], f0); f1 = fmaf(f5v.y, sds[wib][j+5], f1);
            g0 = fmaf(f6v.x, sds[wib][j+6], g0); g1 = fmaf(f6v.y, sds[wib][j+6], g1);
            h0 = fmaf(f7v.x, sds[wib][j+7], h0); h1 = fmaf(f7v.y, sds[wib][j+7], h1);
        }
        for (; j < cnt; j++) {
            float2 fv = __half22float2(((const half2*)(hs + (size_t)sidx[wib][j] * 64))[lane]);
            float ss = sds[wib][j];
            a0 = fmaf(fv.x, ss, a0);
            a1 = fmaf(fv.y, ss, a1);
        }
    }
    a0 = ((a0 + b0) + (c0 + d0)) + ((e0 + f0) + (g0 + h0));
    a1 = ((a1 + b1) + (c1 + d1)) + ((e1 + f1) + (g1 + h1));

    float2 bb = ((const float2*)bias)[lane];
    float o0 = fmaxf(fmaf(a0, rd, bb.x), 0.f);
    float o1 = fmaxf(fmaf(a1, rd, bb.y), 0.f);
    ((half2*)(out + (size_t)w * 64))[lane] = __floats2half2_rn(o0, o1);
}

// ---------------- Side-stream context ----------------
struct SideCtx {
    cudaStream_t side;
    cudaEvent_t evFork, evG1;
    SideCtx() {
        cudaStreamCreateWithFlags(&side, cudaStreamNonBlocking);
        cudaEventCreateWithFlags(&evFork, cudaEventDisableTiming);
        cudaEventCreateWithFlags(&evG1, cudaEventDisableTiming);
    }
};
static SideCtx g_ctx;

// ---------------- Host launcher ----------------
extern "C" void kernel_launch(void* const* d_in, const int* in_sizes, int n_in,
                              void* d_out, int out_size) {
    const float* x  = (const float*)d_in[0];
    const int*   ei = (const int*)d_in[1];
    const float* W1 = (const float*)d_in[2];
    const float* b1 = (const float*)d_in[3];
    const float* W2 = (const float*)d_in[4];
    const float* b2 = (const float*)d_in[5];
    const float* W3 = (const float*)d_in[6];
    const float* b3 = (const float*)d_in[7];
    const float* W4 = (const float*)d_in[8];
    const float* b4 = (const float*)d_in[9];
    float* out = (float*)d_out;

    const int M = in_sizes[0] / 128;
    const int E = in_sizes[1] / 2;

    __half *hb, *ab;
    float *Wf, *bf;
    cudaGetSymbolAddress((void**)&hb, g_h);
    cudaGetSymbolAddress((void**)&ab, g_a);
    cudaGetSymbolAddress((void**)&Wf, g_Wf);
    cudaGetSymbolAddress((void**)&bf, g_bf);

    // smem: sB = K*32 uint32 ; As = 128*(K+8) halfs
    const int smem128 = 128 * 32 * 4 + 128 * 136 * 2;   // 16384 + 34816 = 51200 B
    const int smem64  = 64 * 32 * 4 + 128 * 72 * 2;     // 8192 + 18432  = 26624 B
    cudaFuncSetAttribute((const void*)gemm_mma<128, 0, float, __half>,
                         cudaFuncAttributeMaxDynamicSharedMemorySize, smem128);
    cudaFuncSetAttribute((const void*)gemm_mma<64, 0, __half, __half>,
                         cudaFuncAttributeMaxDynamicSharedMemorySize, smem64);
    cudaFuncSetAttribute((const void*)gemm_mma<64, 1, __half, float>,
                         cudaFuncAttributeMaxDynamicSharedMemorySize, smem64);

    const int gemmBlocks = (M + 127) / 128;
    const int warpBlocks = (M * 32 + 255) / 256;
    const int NBZ = (M + 255) / 256;
    const int scanBlocks = (M + 1023) / 1024;

    // Fork: GEMM1 (no CSR dependency) on side stream || CSR build on main stream.
    cudaEventRecord(g_ctx.evFork, 0);
    cudaStreamWaitEvent(g_ctx.side, g_ctx.evFork, 0);
    gemm_mma<128, 0, float, __half><<<gemmBlocks, 256, smem128, g_ctx.side>>>(x, W1, nullptr, hb, M);
    cudaEventRecord(g_ctx.evG1, g_ctx.side);

    prep_k<<<NBZ + 17, 256>>>(ei, 2 * E, M, W3, W4, b3, b4);
    hist_k<<<(E + 255) / 256, 256>>>(ei, E);
    scan_k<<<scanBlocks, 1024>>>(M, E);
    fill_k<<<(E + 255) / 256, 256>>>(ei, E);

    cudaStreamWaitEvent(0, g_ctx.evG1, 0);
    agg_k<<<warpBlocks, 256>>>(hb, b1, ab, M);
    gemm_mma<64, 0, __half, __half><<<gemmBlocks, 256, smem64>>>(ab, W2, nullptr, hb, M);
    agg_k<<<warpBlocks, 256>>>(hb, b2, ab, M);
    gemm_mma<64, 1, __half, float><<<gemmBlocks, 256, smem64>>>(ab, Wf, bf, out, M);
}